// round 3
// baseline (speedup 1.0000x reference)
#include <cuda_runtime.h>
#include <cuda_bf16.h>

// Token-conditioned hidden-state table: hs depends only on token id (V=64).
__device__ float g_hs_table[64 * 64];

#define H      64
#define VOCAB  64
#define INNER  16
#define LSEQ   2048
#define TSTEPS 1023
#define LRATE  0.01f
#define C2H    (2.0f / 64.0f)

#define CPB    8          // chains (warps) per block
#define NTHR   (CPB * 32)

// ---------------------------------------------------------------------------
// Kernel A: build hs_table[v][h] = LayerNorm(e + FF(e)) for each vocab id v.
// grid(64), block(128)
// ---------------------------------------------------------------------------
__global__ void build_table_kernel(
    const float* __restrict__ embed,   // (64,64)
    const float* __restrict__ ff_w1,   // (64,128)
    const float* __restrict__ ff_b1,   // (128,)
    const float* __restrict__ ff_w2,   // (128,64)
    const float* __restrict__ ff_b2,   // (64,)
    const float* __restrict__ ln_g,    // (64,)
    const float* __restrict__ ln_b)    // (64,)
{
    __shared__ float e_sh[64];
    __shared__ float u_sh[128];
    __shared__ float h_sh[64];

    const int v = blockIdx.x;
    const int t = threadIdx.x;

    if (t < 64) e_sh[t] = embed[v * 64 + t];
    __syncthreads();

    {
        float acc = ff_b1[t];
        #pragma unroll 8
        for (int h = 0; h < 64; ++h)
            acc = fmaf(e_sh[h], ff_w1[h * 128 + t], acc);
        u_sh[t] = fmaxf(acc, 0.0f);
    }
    __syncthreads();

    if (t < 64) {
        float acc = ff_b2[t];
        #pragma unroll 8
        for (int i = 0; i < 128; ++i)
            acc = fmaf(u_sh[i], ff_w2[i * 64 + t], acc);
        h_sh[t] = e_sh[t] + acc;
    }
    __syncthreads();

    if (t < 64) {
        float mu = 0.0f;
        #pragma unroll 8
        for (int h = 0; h < 64; ++h) mu += h_sh[h];
        mu *= (1.0f / 64.0f);
        float var = 0.0f;
        #pragma unroll 8
        for (int h = 0; h < 64; ++h) {
            float d = h_sh[h] - mu;
            var = fmaf(d, d, var);
        }
        var *= (1.0f / 64.0f);
        const float inv = rsqrtf(var + 1e-5f);
        g_hs_table[v * 64 + t] = (h_sh[t] - mu) * inv * ln_g[t] + ln_b[t];
    }
}

// ---------------------------------------------------------------------------
// Kernel B: per-batch TTT chain. One warp per chain, 8 chains per block so
// every SMSP carries 2 independent warps (latency hiding). grid(32), block(256)
// ---------------------------------------------------------------------------
__global__ void __launch_bounds__(NTHR, 1) ttt_kernel(
    const int*   __restrict__ seq,     // (256, 2048) int32
    const float* __restrict__ w1,      // (64,16)
    const float* __restrict__ b1,      // (16,)
    const float* __restrict__ w2,      // (16,64)
    const float* __restrict__ b2,      // (64,)
    const float* __restrict__ out_w,   // (64,64)
    const float* __restrict__ out_b,   // (64,)
    float*       __restrict__ out)     // (256,64)
{
    __shared__ float         tab[VOCAB * H];        // 16 KB
    __shared__ unsigned char tokb[CPB * LSEQ];      // 16 KB (tokens fit in u8)
    __shared__ float         ctx_sh[CPB][H];        // 2 KB

    const int tid = threadIdx.x;
    const int wid = tid >> 5;
    const int t   = tid & 31;
    const int b   = blockIdx.x * CPB + wid;

    // Cooperative staging: hs table + this block's 8 token rows (packed to u8)
    for (int i = tid; i < VOCAB * H; i += NTHR) tab[i] = g_hs_table[i];
    const int* sbase = seq + (size_t)blockIdx.x * CPB * LSEQ;
    for (int i = tid; i < CPB * LSEQ; i += NTHR)
        tokb[i] = (unsigned char)sbase[i];

    // Load initial parameters (shared p0 across batches)
    float W1a[INNER], W1b[INNER], W2a[INNER], W2b[INNER], b1r[INNER];
    #pragma unroll
    for (int j = 0; j < INNER; ++j) {
        W1a[j] = w1[t * INNER + j];
        W1b[j] = w1[(t + 32) * INNER + j];
        W2a[j] = w2[j * H + t];
        W2b[j] = w2[j * H + t + 32];
        b1r[j] = b1[j];
    }
    float b2a = b2[t];
    float b2b = b2[t + 32];

    __syncthreads();

    const unsigned char* myt = tokb + wid * LSEQ;
    float a[INNER], p[INNER];

    #pragma unroll 1
    for (int s = 0; s < TSTEPS; ++s) {
        const unsigned int pair = *(const unsigned short*)(myt + 2 * s);
        const int tk = pair & 0xff;
        const int tv = pair >> 8;
        const float k0 = tab[tk * H + t];
        const float k1 = tab[tk * H + t + 32];
        const float v0 = tab[tv * H + t];
        const float v1 = tab[tv * H + t + 32];

        // ---- forward: z[j] = b1[j] + sum_h k[h] W1[h,j] (cross-lane reduce) ----
        #pragma unroll
        for (int j = 0; j < INNER; ++j)
            p[j] = fmaf(k0, W1a[j], k1 * W1b[j]);
        #pragma unroll
        for (int st = 16; st >= 1; st >>= 1) {
            #pragma unroll
            for (int j = 0; j < INNER; ++j)
                p[j] += __shfl_xor_sync(0xffffffffu, p[j], st);
        }
        #pragma unroll
        for (int j = 0; j < INNER; ++j)
            a[j] = fmaxf(p[j] + b1r[j], 0.0f);   // a>0 <=> z>0 (relu mask)

        // ---- pred[h] = b2[h] + sum_j a[j] W2[j,h] (lane-local, 2 accums) ----
        float pr0 = b2a, pr0x = 0.0f, pr1 = b2b, pr1x = 0.0f;
        #pragma unroll
        for (int j = 0; j < INNER; j += 2) {
            pr0  = fmaf(a[j],     W2a[j],     pr0);
            pr0x = fmaf(a[j + 1], W2a[j + 1], pr0x);
            pr1  = fmaf(a[j],     W2b[j],     pr1);
            pr1x = fmaf(a[j + 1], W2b[j + 1], pr1x);
        }
        const float d0 = C2H * ((pr0 + pr0x) - v0);
        const float d1 = C2H * ((pr1 + pr1x) - v1);

        // ---- da[j] = sum_h d[h] W2_old[j,h] (reduce, BEFORE W2 update) ----
        #pragma unroll
        for (int j = 0; j < INNER; ++j)
            p[j] = fmaf(d0, W2a[j], d1 * W2b[j]);
        #pragma unroll
        for (int st = 16; st >= 1; st >>= 1) {
            #pragma unroll
            for (int j = 0; j < INNER; ++j)
                p[j] += __shfl_xor_sync(0xffffffffu, p[j], st);
        }

        // ---- update W2, b2: dW2[j,h] = a[j]*d[h] ----
        const float l0 = LRATE * d0;
        const float l1 = LRATE * d1;
        #pragma unroll
        for (int j = 0; j < INNER; ++j) {
            W2a[j] = fmaf(-l0, a[j], W2a[j]);
            W2b[j] = fmaf(-l1, a[j], W2b[j]);
        }
        b2a -= l0;
        b2b -= l1;

        // ---- dz = da * (z>0); update W1, b1 ----
        const float m0 = LRATE * k0;
        const float m1 = LRATE * k1;
        #pragma unroll
        for (int j = 0; j < INNER; ++j) {
            const float dz = (a[j] > 0.0f) ? p[j] : 0.0f;
            W1a[j] = fmaf(-m0, dz, W1a[j]);
            W1b[j] = fmaf(-m1, dz, W1b[j]);
            b1r[j] = fmaf(-LRATE, dz, b1r[j]);
        }
    }

    // ---- final forward with q = hs[:, L-1], then logits ----
    {
        const int tq = myt[LSEQ - 1];
        const float q0 = tab[tq * H + t];
        const float q1 = tab[tq * H + t + 32];
        #pragma unroll
        for (int j = 0; j < INNER; ++j)
            p[j] = fmaf(q0, W1a[j], q1 * W1b[j]);
        #pragma unroll
        for (int st = 16; st >= 1; st >>= 1) {
            #pragma unroll
            for (int j = 0; j < INNER; ++j)
                p[j] += __shfl_xor_sync(0xffffffffu, p[j], st);
        }
        #pragma unroll
        for (int j = 0; j < INNER; ++j)
            a[j] = fmaxf(p[j] + b1r[j], 0.0f);

        float c0 = b2a, c1 = b2b;
        #pragma unroll
        for (int j = 0; j < INNER; ++j) {
            c0 = fmaf(a[j], W2a[j], c0);
            c1 = fmaf(a[j], W2b[j], c1);
        }
        ctx_sh[wid][t]      = c0;
        ctx_sh[wid][t + 32] = c1;
    }
    __syncwarp();

    // out[b, o] = out_b[o] + sum_h ctx[h] * out_w[h, o];  lane handles o = t, t+32
    #pragma unroll
    for (int half = 0; half < 2; ++half) {
        const int o = t + half * 32;
        float acc = out_b[o];
        #pragma unroll 8
        for (int h = 0; h < H; ++h)
            acc = fmaf(ctx_sh[wid][h], out_w[h * 64 + o], acc);
        out[b * 64 + o] = acc;
    }
}

// ---------------------------------------------------------------------------
// Launch
// Inputs (metadata order): 0 seq(i32), 1 embed, 2 ff_w1, 3 ff_b1, 4 ff_w2,
// 5 ff_b2, 6 ln_g, 7 ln_b, 8 w1, 9 b1, 10 w2, 11 b2, 12 out_w, 13 out_b
// ---------------------------------------------------------------------------
extern "C" void kernel_launch(void* const* d_in, const int* in_sizes, int n_in,
                              void* d_out, int out_size)
{
    const int*   seq    = (const int*)  d_in[0];
    const float* embed  = (const float*)d_in[1];
    const float* ff_w1  = (const float*)d_in[2];
    const float* ff_b1  = (const float*)d_in[3];
    const float* ff_w2  = (const float*)d_in[4];
    const float* ff_b2  = (const float*)d_in[5];
    const float* ln_g   = (const float*)d_in[6];
    const float* ln_b   = (const float*)d_in[7];
    const float* w1     = (const float*)d_in[8];
    const float* b1     = (const float*)d_in[9];
    const float* w2     = (const float*)d_in[10];
    const float* b2     = (const float*)d_in[11];
    const float* out_w  = (const float*)d_in[12];
    const float* out_b  = (const float*)d_in[13];
    float*       out    = (float*)d_out;

    build_table_kernel<<<64, 128>>>(embed, ff_w1, ff_b1, ff_w2, ff_b2, ln_g, ln_b);
    ttt_kernel<<<256 / CPB, NTHR>>>(seq, w1, b1, w2, b2, out_w, out_b, out);
}

// round 4
// speedup vs baseline: 1.4292x; 1.4292x over previous
#include <cuda_runtime.h>
#include <cuda_bf16.h>

// Token-conditioned tables: hs depends only on token id (V=64).
__device__ float g_hs_table[64 * 64];
__device__ float g_gram[64 * 64];     // gram[u][v] = hs_u . hs_v

#define H      64
#define VOCAB  64
#define INNER  16
#define LSEQ   2048
#define TSTEPS 1023
#define LRATE  0.01f
#define C2H    (2.0f / 64.0f)

#define CPB    2          // chains (warps) per block
#define NTHR   (CPB * 32)

// ---------------------------------------------------------------------------
// Kernel A: build hs_table[v][h] = LayerNorm(e + FF(e)) for each vocab id v.
// grid(64), block(128)
// ---------------------------------------------------------------------------
__global__ void build_table_kernel(
    const float* __restrict__ embed,   // (64,64)
    const float* __restrict__ ff_w1,   // (64,128)
    const float* __restrict__ ff_b1,   // (128,)
    const float* __restrict__ ff_w2,   // (128,64)
    const float* __restrict__ ff_b2,   // (64,)
    const float* __restrict__ ln_g,    // (64,)
    const float* __restrict__ ln_b)    // (64,)
{
    __shared__ float e_sh[64];
    __shared__ float u_sh[128];
    __shared__ float h_sh[64];

    const int v = blockIdx.x;
    const int t = threadIdx.x;

    if (t < 64) e_sh[t] = embed[v * 64 + t];
    __syncthreads();

    {
        float acc = ff_b1[t];
        #pragma unroll 8
        for (int h = 0; h < 64; ++h)
            acc = fmaf(e_sh[h], ff_w1[h * 128 + t], acc);
        u_sh[t] = fmaxf(acc, 0.0f);
    }
    __syncthreads();

    if (t < 64) {
        float acc = ff_b2[t];
        #pragma unroll 8
        for (int i = 0; i < 128; ++i)
            acc = fmaf(u_sh[i], ff_w2[i * 64 + t], acc);
        h_sh[t] = e_sh[t] + acc;
    }
    __syncthreads();

    if (t < 64) {
        float mu = 0.0f;
        #pragma unroll 8
        for (int h = 0; h < 64; ++h) mu += h_sh[h];
        mu *= (1.0f / 64.0f);
        float var = 0.0f;
        #pragma unroll 8
        for (int h = 0; h < 64; ++h) {
            float d = h_sh[h] - mu;
            var = fmaf(d, d, var);
        }
        var *= (1.0f / 64.0f);
        const float inv = rsqrtf(var + 1e-5f);
        g_hs_table[v * 64 + t] = (h_sh[t] - mu) * inv * ln_g[t] + ln_b[t];
    }
}

// ---------------------------------------------------------------------------
// Kernel A2: gram[u][v] = hs_u . hs_v.  grid(64), block(64)
// ---------------------------------------------------------------------------
__global__ void gram_kernel()
{
    __shared__ float T[VOCAB * H];
    const int u = blockIdx.x;
    const int v = threadIdx.x;
    for (int i = v; i < VOCAB * H; i += 64) T[i] = g_hs_table[i];
    __syncthreads();
    float acc = 0.0f;
    #pragma unroll 8
    for (int h = 0; h < H; ++h)
        acc = fmaf(T[u * H + h], T[v * H + h], acc);
    g_gram[u * 64 + v] = acc;
}

// ---------------------------------------------------------------------------
// Kernel B: per-batch TTT chain with one-step lookahead of the forward
// reduction (rank-1 Gram correction). One warp per chain. grid(128), block(64)
// ---------------------------------------------------------------------------
__global__ void __launch_bounds__(NTHR, 1) ttt_kernel(
    const int*   __restrict__ seq,     // (256, 2048) int32
    const float* __restrict__ w1,      // (64,16)
    const float* __restrict__ b1,      // (16,)
    const float* __restrict__ w2,      // (16,64)
    const float* __restrict__ b2,      // (64,)
    const float* __restrict__ out_w,   // (64,64)
    const float* __restrict__ out_b,   // (64,)
    float*       __restrict__ out)     // (256,64)
{
    __shared__ float         tab[VOCAB * H];     // 16 KB
    __shared__ float         gram[VOCAB * 64];   // 16 KB
    __shared__ unsigned char tokb[CPB * LSEQ];   // 4 KB
    __shared__ float         ctx_sh[CPB][H];

    const int tid = threadIdx.x;
    const int wid = tid >> 5;
    const int t   = tid & 31;
    const int b   = blockIdx.x * CPB + wid;

    // Cooperative staging
    for (int i = tid; i < VOCAB * H; i += NTHR) {
        tab[i]  = g_hs_table[i];
        gram[i] = g_gram[i];
    }
    const int* sbase = seq + (size_t)blockIdx.x * CPB * LSEQ;
    for (int i = tid; i < CPB * LSEQ; i += NTHR)
        tokb[i] = (unsigned char)sbase[i];

    // Load initial parameters (shared p0 across batches)
    float W1a[INNER], W1b[INNER], W2a[INNER], W2b[INNER], b1r[INNER];
    #pragma unroll
    for (int j = 0; j < INNER; ++j) {
        W1a[j] = w1[t * INNER + j];
        W1b[j] = w1[(t + 32) * INNER + j];
        W2a[j] = w2[j * H + t];
        W2b[j] = w2[j * H + t + 32];
        b1r[j] = b1[j];
    }
    float b2a = b2[t];
    float b2b = b2[t + 32];

    __syncthreads();

    // Patch: slot 2046 (unused k of a would-be step 1023) <- query token 2047,
    // so the last lookahead computes the final-forward z for free.
    if (tid < CPB) tokb[tid * LSEQ + (LSEQ - 2)] = tokb[tid * LSEQ + (LSEQ - 1)];
    __syncthreads();

    const unsigned char* myt = tokb + wid * LSEQ;

    float zs[INNER], a[INNER], p[INNER];

    // ---- prologue: zs = W1_0^T k_0 (full butterfly reduce) ----
    int   tk = myt[0];
    float k0 = tab[tk * H + t];
    float k1 = tab[tk * H + t + 32];
    #pragma unroll
    for (int j = 0; j < INNER; ++j)
        zs[j] = fmaf(k0, W1a[j], k1 * W1b[j]);
    #pragma unroll
    for (int st = 16; st >= 1; st >>= 1) {
        #pragma unroll
        for (int j = 0; j < INNER; ++j)
            zs[j] += __shfl_xor_sync(0xffffffffu, zs[j], st);
    }

    #pragma unroll 1
    for (int s = 0; s < TSTEPS; ++s) {
        const int tv = myt[2 * s + 1];
        const int tn = myt[2 * s + 2];           // next k (or query at s=1022)
        const float v0  = tab[tv * H + t];
        const float v1  = tab[tv * H + t + 32];
        const float kn0 = tab[tn * H + t];
        const float kn1 = tab[tn * H + t + 32];
        const float gkk = gram[tk * 64 + tn];    // k_s . k_{s+1}

        // ---- a = relu(z + b1) ----
        #pragma unroll
        for (int j = 0; j < INNER; ++j)
            a[j] = fmaxf(zs[j] + b1r[j], 0.0f);

        // ---- pred[h] = b2[h] + sum_j a[j] W2[j,h] (lane-local) ----
        float pr0 = b2a, pr0x = 0.0f, pr1 = b2b, pr1x = 0.0f;
        #pragma unroll
        for (int j = 0; j < INNER; j += 2) {
            pr0  = fmaf(a[j],     W2a[j],     pr0);
            pr0x = fmaf(a[j + 1], W2a[j + 1], pr0x);
            pr1  = fmaf(a[j],     W2b[j],     pr1);
            pr1x = fmaf(a[j + 1], W2b[j + 1], pr1x);
        }
        const float d0 = C2H * ((pr0 + pr0x) - v0);
        const float d1 = C2H * ((pr1 + pr1x) - v1);

        // ---- partials: da (old W2) and next-z (old W1, pre-update) ----
        #pragma unroll
        for (int j = 0; j < INNER; ++j) {
            p[j]  = fmaf(d0,  W2a[j], d1  * W2b[j]);
            zs[j] = fmaf(kn0, W1a[j], kn1 * W1b[j]);
        }

        // ---- two interleaved 32-lane butterflies (da critical, zs hidden) ----
        #pragma unroll
        for (int st = 16; st >= 1; st >>= 1) {
            #pragma unroll
            for (int j = 0; j < INNER; ++j)
                p[j] += __shfl_xor_sync(0xffffffffu, p[j], st);
            #pragma unroll
            for (int j = 0; j < INNER; ++j)
                zs[j] += __shfl_xor_sync(0xffffffffu, zs[j], st);
        }

        // ---- update W2, b2: dW2[j,h] = a[j]*d[h] ----
        const float l0 = LRATE * d0;
        const float l1 = LRATE * d1;
        #pragma unroll
        for (int j = 0; j < INNER; ++j) {
            W2a[j] = fmaf(-l0, a[j], W2a[j]);
            W2b[j] = fmaf(-l1, a[j], W2b[j]);
        }
        b2a -= l0;
        b2b -= l1;

        // ---- dz; update W1, b1; correct looked-ahead z with Gram rank-1 ----
        const float m0 = LRATE * k0;
        const float m1 = LRATE * k1;
        const float gl = LRATE * gkk;
        #pragma unroll
        for (int j = 0; j < INNER; ++j) {
            const float dz = (a[j] > 0.0f) ? p[j] : 0.0f;
            W1a[j] = fmaf(-m0, dz, W1a[j]);
            W1b[j] = fmaf(-m1, dz, W1b[j]);
            b1r[j] = fmaf(-LRATE, dz, b1r[j]);
            zs[j]  = fmaf(-gl, dz, zs[j]);
        }

        k0 = kn0; k1 = kn1; tk = tn;
    }

    // ---- final forward: zs already holds W1_final^T q ----
    {
        #pragma unroll
        for (int j = 0; j < INNER; ++j)
            a[j] = fmaxf(zs[j] + b1r[j], 0.0f);

        float c0 = b2a, c1 = b2b;
        #pragma unroll
        for (int j = 0; j < INNER; ++j) {
            c0 = fmaf(a[j], W2a[j], c0);
            c1 = fmaf(a[j], W2b[j], c1);
        }
        ctx_sh[wid][t]      = c0;
        ctx_sh[wid][t + 32] = c1;
    }
    __syncwarp();

    // out[b, o] = out_b[o] + sum_h ctx[h] * out_w[h, o]
    #pragma unroll
    for (int half = 0; half < 2; ++half) {
        const int o = t + half * 32;
        float acc = out_b[o];
        #pragma unroll 8
        for (int h = 0; h < H; ++h)
            acc = fmaf(ctx_sh[wid][h], out_w[h * 64 + o], acc);
        out[b * 64 + o] = acc;
    }
}

// ---------------------------------------------------------------------------
// Launch
// Inputs (metadata order): 0 seq(i32), 1 embed, 2 ff_w1, 3 ff_b1, 4 ff_w2,
// 5 ff_b2, 6 ln_g, 7 ln_b, 8 w1, 9 b1, 10 w2, 11 b2, 12 out_w, 13 out_b
// ---------------------------------------------------------------------------
extern "C" void kernel_launch(void* const* d_in, const int* in_sizes, int n_in,
                              void* d_out, int out_size)
{
    const int*   seq    = (const int*)  d_in[0];
    const float* embed  = (const float*)d_in[1];
    const float* ff_w1  = (const float*)d_in[2];
    const float* ff_b1  = (const float*)d_in[3];
    const float* ff_w2  = (const float*)d_in[4];
    const float* ff_b2  = (const float*)d_in[5];
    const float* ln_g   = (const float*)d_in[6];
    const float* ln_b   = (const float*)d_in[7];
    const float* w1     = (const float*)d_in[8];
    const float* b1     = (const float*)d_in[9];
    const float* w2     = (const float*)d_in[10];
    const float* b2     = (const float*)d_in[11];
    const float* out_w  = (const float*)d_in[12];
    const float* out_b  = (const float*)d_in[13];
    float*       out    = (float*)d_out;

    build_table_kernel<<<64, 128>>>(embed, ff_w1, ff_b1, ff_w2, ff_b2, ln_g, ln_b);
    gram_kernel<<<64, 64>>>();
    ttt_kernel<<<256 / CPB, NTHR>>>(seq, w1, b1, w2, b2, out_w, out_b, out);
}

// round 7
// speedup vs baseline: 2.5011x; 1.7500x over previous
#include <cuda_runtime.h>
#include <cuda_bf16.h>

// Token-conditioned tables: hs depends only on token id (V=64).
__device__ float g_hs_table[64 * 64];
__device__ float g_gram[64 * 64];     // gram[u][v] = hs_u . hs_v

#define H      64
#define VOCAB  64
#define INNER  16
#define LSEQ   2048
#define TSTEPS 1023
#define LRATE  0.01f
#define C2H    (2.0f / 64.0f)

#define CPB    2          // chains (warps) per block
#define NTHR   (CPB * 32)

#define SHX(v, m) __shfl_xor_sync(0xffffffffu, (v), (m))

// ---------------------------------------------------------------------------
// Kernel A: build hs_table[v][h] = LayerNorm(e + FF(e)) for each vocab id v.
// ---------------------------------------------------------------------------
__global__ void build_table_kernel(
    const float* __restrict__ embed,   // (64,64)
    const float* __restrict__ ff_w1,   // (64,128)
    const float* __restrict__ ff_b1,   // (128,)
    const float* __restrict__ ff_w2,   // (128,64)
    const float* __restrict__ ff_b2,   // (64,)
    const float* __restrict__ ln_g,    // (64,)
    const float* __restrict__ ln_b)    // (64,)
{
    __shared__ float e_sh[64];
    __shared__ float u_sh[128];
    __shared__ float h_sh[64];

    const int v = blockIdx.x;
    const int t = threadIdx.x;

    if (t < 64) e_sh[t] = embed[v * 64 + t];
    __syncthreads();

    {
        float acc = ff_b1[t];
        #pragma unroll 8
        for (int h = 0; h < 64; ++h)
            acc = fmaf(e_sh[h], ff_w1[h * 128 + t], acc);
        u_sh[t] = fmaxf(acc, 0.0f);
    }
    __syncthreads();

    if (t < 64) {
        float acc = ff_b2[t];
        #pragma unroll 8
        for (int i = 0; i < 128; ++i)
            acc = fmaf(u_sh[i], ff_w2[i * 64 + t], acc);
        h_sh[t] = e_sh[t] + acc;
    }
    __syncthreads();

    if (t < 64) {
        float mu = 0.0f;
        #pragma unroll 8
        for (int h = 0; h < 64; ++h) mu += h_sh[h];
        mu *= (1.0f / 64.0f);
        float var = 0.0f;
        #pragma unroll 8
        for (int h = 0; h < 64; ++h) {
            float d = h_sh[h] - mu;
            var = fmaf(d, d, var);
        }
        var *= (1.0f / 64.0f);
        const float inv = rsqrtf(var + 1e-5f);
        g_hs_table[v * 64 + t] = (h_sh[t] - mu) * inv * ln_g[t] + ln_b[t];
    }
}

// ---------------------------------------------------------------------------
// Kernel A2: gram[u][v] = hs_u . hs_v.  grid(64), block(64)
// ---------------------------------------------------------------------------
__global__ void gram_kernel()
{
    __shared__ float T[VOCAB * H];
    const int u = blockIdx.x;
    const int v = threadIdx.x;
    for (int i = v; i < VOCAB * H; i += 64) T[i] = g_hs_table[i];
    __syncthreads();
    float acc = 0.0f;
    #pragma unroll 8
    for (int h = 0; h < H; ++h)
        acc = fmaf(T[u * H + h], T[v * H + h], acc);
    g_gram[u * 64 + v] = acc;
}

// ---------------------------------------------------------------------------
// XOR-permuted all-reduce over 32 lanes for a 16-vector (lane ℓ reg m holds
// absolute index jown(ℓ)^m, jown = (ℓ>>1)&15).
// Reduce: 16 SHFL + 16 ADD. Gather: 15 SHFL. Result again permuted-full.
// ---------------------------------------------------------------------------
__device__ __forceinline__ void perm_reduce(float* p) {
    #pragma unroll
    for (int m = 0; m < 8; ++m) p[m] += SHX(p[m ^ 8], 16);
    #pragma unroll
    for (int m = 0; m < 4; ++m) p[m] += SHX(p[m ^ 4], 8);
    #pragma unroll
    for (int m = 0; m < 2; ++m) p[m] += SHX(p[m ^ 2], 4);
    p[0] += SHX(p[1], 2);
    p[0] += SHX(p[0], 1);
}
__device__ __forceinline__ void perm_gather(float* p) {
    p[1] = SHX(p[0], 2);
    #pragma unroll
    for (int m = 0; m < 2; ++m) p[2 + m] = SHX(p[m], 4);
    #pragma unroll
    for (int m = 0; m < 4; ++m) p[4 + m] = SHX(p[m], 8);
    #pragma unroll
    for (int m = 0; m < 8; ++m) p[8 + m] = SHX(p[m], 16);
}

// ---------------------------------------------------------------------------
// Kernel B: per-batch TTT chain; Gram lookahead + permuted halving reductions.
// One warp per chain. grid(128), block(64)
// ---------------------------------------------------------------------------
__global__ void __launch_bounds__(NTHR, 1) ttt_kernel(
    const int*   __restrict__ seq,     // (256, 2048) int32
    const float* __restrict__ w1,      // (64,16)
    const float* __restrict__ b1,      // (16,)
    const float* __restrict__ w2,      // (16,64)
    const float* __restrict__ b2,      // (64,)
    const float* __restrict__ out_w,   // (64,64)
    const float* __restrict__ out_b,   // (64,)
    float*       __restrict__ out)     // (256,64)
{
    __shared__ float         tab[VOCAB * H];     // 16 KB
    __shared__ float         gram[VOCAB * 64];   // 16 KB
    __shared__ unsigned char tokb[CPB * LSEQ];   // 4 KB
    __shared__ float         ctx_sh[CPB][H];

    const int tid  = threadIdx.x;
    const int wid  = tid >> 5;
    const int t    = tid & 31;
    const int b    = blockIdx.x * CPB + wid;
    const int jown = (t >> 1) & 15;              // per-lane XOR permutation base

    // Cooperative staging
    for (int i = tid; i < VOCAB * H; i += NTHR) {
        tab[i]  = g_hs_table[i];
        gram[i] = g_gram[i];
    }
    const int* sbase = seq + (size_t)blockIdx.x * CPB * LSEQ;
    for (int i = tid; i < CPB * LSEQ; i += NTHR)
        tokb[i] = (unsigned char)sbase[i];

    // Load initial parameters in per-lane permuted j-order (j = jown ^ m)
    float W1a[INNER], W1b[INNER], W2a[INNER], W2b[INNER], b1r[INNER];
    #pragma unroll
    for (int m = 0; m < INNER; ++m) {
        const int j = jown ^ m;
        W1a[m] = w1[t * INNER + j];
        W1b[m] = w1[(t + 32) * INNER + j];
        W2a[m] = w2[j * H + t];
        W2b[m] = w2[j * H + t + 32];
        b1r[m] = b1[j];
    }
    float b2a = b2[t];
    float b2b = b2[t + 32];

    __syncthreads();

    // Patch: slot 2046 (unused k of would-be step 1023) <- query token 2047,
    // so the last lookahead computes the final-forward z for free.
    if (tid < CPB) tokb[tid * LSEQ + (LSEQ - 2)] = tokb[tid * LSEQ + (LSEQ - 1)];
    __syncthreads();

    const unsigned char* myt = tokb + wid * LSEQ;

    float zs[INNER], a[INNER], p[INNER];

    // ---- prologue: zs = W1_0^T k_0 (permuted reduce + gather) ----
    int   tk = myt[0];
    float k0 = tab[tk * H + t];
    float k1 = tab[tk * H + t + 32];
    #pragma unroll
    for (int m = 0; m < INNER; ++m)
        zs[m] = fmaf(k0, W1a[m], k1 * W1b[m]);
    perm_reduce(zs);
    perm_gather(zs);

    #pragma unroll 1
    for (int s = 0; s < TSTEPS; ++s) {
        const int tv = myt[2 * s + 1];
        const int tn = myt[2 * s + 2];           // next k (or query at s=1022)
        const float v0  = tab[tv * H + t];
        const float v1  = tab[tv * H + t + 32];
        const float kn0 = tab[tn * H + t];
        const float kn1 = tab[tn * H + t + 32];
        const float gkk = gram[tk * 64 + tn];    // k_s . k_{s+1}

        // ---- a = relu(z + b1) ----
        #pragma unroll
        for (int m = 0; m < INNER; ++m)
            a[m] = fmaxf(zs[m] + b1r[m], 0.0f);

        // ---- pred[h] = b2[h] + sum_j a[j] W2[j,h] (lane-local, 4 accums) ----
        float p0a = b2a, p0b = 0.0f, p0c = 0.0f, p0d = 0.0f;
        float p1a = b2b, p1b = 0.0f, p1c = 0.0f, p1d = 0.0f;
        #pragma unroll
        for (int m = 0; m < INNER; m += 4) {
            p0a = fmaf(a[m],     W2a[m],     p0a);
            p0b = fmaf(a[m + 1], W2a[m + 1], p0b);
            p0c = fmaf(a[m + 2], W2a[m + 2], p0c);
            p0d = fmaf(a[m + 3], W2a[m + 3], p0d);
            p1a = fmaf(a[m],     W2b[m],     p1a);
            p1b = fmaf(a[m + 1], W2b[m + 1], p1b);
            p1c = fmaf(a[m + 2], W2b[m + 2], p1c);
            p1d = fmaf(a[m + 3], W2b[m + 3], p1d);
        }
        const float d0 = C2H * (((p0a + p0b) + (p0c + p0d)) - v0);
        const float d1 = C2H * (((p1a + p1b) + (p1c + p1d)) - v1);

        // ---- partials: da (old W2) and next-z (old W1, pre-update) ----
        #pragma unroll
        for (int m = 0; m < INNER; ++m) {
            p[m]  = fmaf(d0,  W2a[m], d1  * W2b[m]);
            zs[m] = fmaf(kn0, W1a[m], kn1 * W1b[m]);
        }

        // ---- two interleaved permuted all-reduces (31 SHFL + 16 ADD each) ----
        #pragma unroll
        for (int m = 0; m < 8; ++m) p[m]  += SHX(p[m ^ 8], 16);
        #pragma unroll
        for (int m = 0; m < 8; ++m) zs[m] += SHX(zs[m ^ 8], 16);
        #pragma unroll
        for (int m = 0; m < 4; ++m) p[m]  += SHX(p[m ^ 4], 8);
        #pragma unroll
        for (int m = 0; m < 4; ++m) zs[m] += SHX(zs[m ^ 4], 8);
        #pragma unroll
        for (int m = 0; m < 2; ++m) p[m]  += SHX(p[m ^ 2], 4);
        #pragma unroll
        for (int m = 0; m < 2; ++m) zs[m] += SHX(zs[m ^ 2], 4);
        p[0]  += SHX(p[1], 2);
        zs[0] += SHX(zs[1], 2);
        p[0]  += SHX(p[0], 1);
        zs[0] += SHX(zs[0], 1);
        // gather back to permuted-full
        p[1]  = SHX(p[0], 2);
        zs[1] = SHX(zs[0], 2);
        #pragma unroll
        for (int m = 0; m < 2; ++m) { p[2 + m] = SHX(p[m], 4);  zs[2 + m] = SHX(zs[m], 4); }
        #pragma unroll
        for (int m = 0; m < 4; ++m) { p[4 + m] = SHX(p[m], 8);  zs[4 + m] = SHX(zs[m], 8); }
        #pragma unroll
        for (int m = 0; m < 8; ++m) { p[8 + m] = SHX(p[m], 16); zs[8 + m] = SHX(zs[m], 16); }

        // ---- update W2, b2: dW2[j,h] = a[j]*d[h] ----
        const float l0 = LRATE * d0;
        const float l1 = LRATE * d1;
        #pragma unroll
        for (int m = 0; m < INNER; ++m) {
            W2a[m] = fmaf(-l0, a[m], W2a[m]);
            W2b[m] = fmaf(-l1, a[m], W2b[m]);
        }
        b2a -= l0;
        b2b -= l1;

        // ---- dz; update W1, b1; correct looked-ahead z with Gram rank-1 ----
        const float m0 = LRATE * k0;
        const float m1 = LRATE * k1;
        const float gl = LRATE * gkk;
        #pragma unroll
        for (int m = 0; m < INNER; ++m) {
            const float dz = (a[m] > 0.0f) ? p[m] : 0.0f;
            W1a[m] = fmaf(-m0, dz, W1a[m]);
            W1b[m] = fmaf(-m1, dz, W1b[m]);
            b1r[m] = fmaf(-LRATE, dz, b1r[m]);
            zs[m]  = fmaf(-gl, dz, zs[m]);
        }

        k0 = kn0; k1 = kn1; tk = tn;
    }

    // ---- final forward: zs already holds W1_final^T q ----
    {
        #pragma unroll
        for (int m = 0; m < INNER; ++m)
            a[m] = fmaxf(zs[m] + b1r[m], 0.0f);

        float c0 = b2a, c1 = b2b;
        #pragma unroll
        for (int m = 0; m < INNER; ++m) {
            c0 = fmaf(a[m], W2a[m], c0);
            c1 = fmaf(a[m], W2b[m], c1);
        }
        ctx_sh[wid][t]      = c0;
        ctx_sh[wid][t + 32] = c1;
    }
    __syncwarp();

    // out[b, o] = out_b[o] + sum_h ctx[h] * out_w[h, o]
    #pragma unroll
    for (int half = 0; half < 2; ++half) {
        const int o = t + half * 32;
        float acc = out_b[o];
        #pragma unroll 8
        for (int h = 0; h < H; ++h)
            acc = fmaf(ctx_sh[wid][h], out_w[h * 64 + o], acc);
        out[b * 64 + o] = acc;
    }
}

// ---------------------------------------------------------------------------
// Launch
// Inputs (metadata order): 0 seq(i32), 1 embed, 2 ff_w1, 3 ff_b1, 4 ff_w2,
// 5 ff_b2, 6 ln_g, 7 ln_b, 8 w1, 9 b1, 10 w2, 11 b2, 12 out_w, 13 out_b
// ---------------------------------------------------------------------------
extern "C" void kernel_launch(void* const* d_in, const int* in_sizes, int n_in,
                              void* d_out, int out_size)
{
    const int*   seq    = (const int*)  d_in[0];
    const float* embed  = (const float*)d_in[1];
    const float* ff_w1  = (const float*)d_in[2];
    const float* ff_b1  = (const float*)d_in[3];
    const float* ff_w2  = (const float*)d_in[4];
    const float* ff_b2  = (const float*)d_in[5];
    const float* ln_g   = (const float*)d_in[6];
    const float* ln_b   = (const float*)d_in[7];
    const float* w1     = (const float*)d_in[8];
    const float* b1     = (const float*)d_in[9];
    const float* w2     = (const float*)d_in[10];
    const float* b2     = (const float*)d_in[11];
    const float* out_w  = (const float*)d_in[12];
    const float* out_b  = (const float*)d_in[13];
    float*       out    = (float*)d_out;

    build_table_kernel<<<64, 128>>>(embed, ff_w1, ff_b1, ff_w2, ff_b2, ln_g, ln_b);
    gram_kernel<<<64, 64>>>();
    ttt_kernel<<<256 / CPB, NTHR>>>(seq, w1, b1, w2, b2, out_w, out_b, out);
}